// round 12
// baseline (speedup 1.0000x reference)
#include <cuda_runtime.h>
#include <cstdint>

#define T_MAX 32768
#define H 256
#define NTHREADS 256
#define THRESH 0.12f

__device__ float g_ev_x[T_MAX + 8];
__device__ float g_ev_dt[T_MAX + 8];
__device__ int   g_ev_t[T_MAX + 8];
__device__ int   g_evmap[T_MAX];
__device__ int   g_ne;
__device__ float g_hhist[(size_t)T_MAX * H];
__device__ float g_pred[T_MAX + 8];

__device__ __forceinline__ uint32_t smem_u32(const void* p) {
    uint32_t a;
    asm("{ .reg .u64 t; cvta.to.shared.u64 t, %1; cvt.u32.u64 %0, t; }" : "=r"(a) : "l"(p));
    return a;
}
__device__ __forceinline__ uint32_t mapa_u32(uint32_t laddr, uint32_t rank) {
    uint32_t r;
    asm("mapa.shared::cluster.u32 %0, %1, %2;" : "=r"(r) : "r"(laddr), "r"(rank));
    return r;
}
__device__ __forceinline__ uint32_t my_ctarank() {
    uint32_t r; asm("mov.u32 %0, %%cluster_ctarank;" : "=r"(r)); return r;
}
__device__ __forceinline__ float tanh_fast(float x) {
    float r; asm("tanh.approx.f32 %0, %1;" : "=f"(r) : "f"(x)); return r;
}

#define MBARRIER_INIT(addr, cnt) \
    asm volatile("mbarrier.init.shared.b64 [%0], %1;" :: "r"(addr), "r"((uint32_t)(cnt)) : "memory")
#define MBARRIER_EXPECT_TX(addr, tx) \
    asm volatile("mbarrier.arrive.expect_tx.shared.b64 _, [%0], %1;" :: "r"(addr), "r"((uint32_t)(tx)) : "memory")
#define MBARRIER_WAIT(mb, ph) do {                                                   \
    uint32_t _m = (mb), _p = (ph);                                                   \
    asm volatile("{ .reg .pred P1;\n"                                                \
        "WL_%=: mbarrier.try_wait.parity.acquire.cluster.shared::cta.b64 P1, [%0], %1, 0x989680;\n" \
        " @P1 bra.uni WD_%=;\n bra.uni WL_%=;\nWD_%=: }"                              \
        :: "r"(_m), "r"(_p) : "memory");                                             \
} while (0)
#define ST_ASYNC_B32(raddr, v, rmbar) \
    asm volatile("st.async.shared::cluster.mbarrier::complete_tx::bytes.b32 [%0], %1, [%2];" \
                 :: "r"(raddr), "r"(v), "r"(rmbar) : "memory")
#define CLUSTER_SYNC() do {                                       \
    asm volatile("barrier.cluster.arrive.aligned;" ::: "memory"); \
    asm volatile("barrier.cluster.wait.aligned;" ::: "memory");   \
} while (0)
#define BAR_ARRIVE(id, n) asm volatile("bar.arrive %0, %1;" :: "r"(id), "r"(n) : "memory")
#define BAR_SYNC(id, n)   asm volatile("bar.sync %0, %1;"   :: "r"(id), "r"(n) : "memory")
#define FMA2(acc, a, b) asm("fma.rn.f32x2 %0, %1, %2, %0;" : "+l"(acc) : "l"(a), "l"(b))

// ---- Pass 1: exact sequential event scan -----------------------------------
__global__ void k_scan(const float* __restrict__ x, int T) {
    if (threadIdx.x != 0) return;
    float last_val = x[0] + 1.24f;   // (float)(2*0.12 + 1.0)
    float last_t = 0.0f;
    int ne = 0;
    const float4* x4 = reinterpret_cast<const float4*>(x);
    int t = 0;
    for (int b = 0; b < T / 4; ++b) {
        float4 v = __ldg(&x4[b]);
        float xs[4] = {v.x, v.y, v.z, v.w};
        #pragma unroll
        for (int i = 0; i < 4; ++i) {
            float xt = xs[i];
            if (fabsf(xt - last_val) >= THRESH) {
                g_ev_x[ne]  = xt;
                g_ev_dt[ne] = ((float)t - last_t) / 100.0f;
                g_ev_t[ne]  = t;
                last_val = xt; last_t = (float)t;
                ++ne;
            }
            g_evmap[t] = ne - 1;
            ++t;
        }
    }
    g_ne = ne;
    for (int i = 0; i < 8; ++i) { g_ev_x[ne + i] = 0.f; g_ev_dt[ne + i] = 0.f; }
}

// ---- Pass 2: 8-CTA cluster GRU (champion; lead=warp7, split bar,
//      rearm off wake path, self-send last) ----------------------------------
__global__ void __cluster_dims__(8, 1, 1) __launch_bounds__(NTHREADS, 1)
k_main(const float* __restrict__ w_ih, const float* __restrict__ w_hh,
       const float* __restrict__ b_ih, const float* __restrict__ b_hh)
{
    __shared__ __align__(16) float sh_h[2][H];
    __shared__ __align__(16) float s_red[3][32][12];   // [gate][lane][slot]
    __shared__ __align__(8) unsigned long long s_mbar[2];

    const int tid = threadIdx.x;
    const int w   = tid >> 5;
    const int l   = tid & 31;
    // XOR-swizzled slot: conflict-free STS (R9 win)
    const int slot = w ^ ((l >> 2) & 7);
    const uint32_t rank = my_ctarank();
    const int j = (int)rank * 32 + l;

    // register-resident w_hh rows {j, H+j, 2H+j}, cols [32w, 32w+32)
    unsigned long long wv[3][16];
    #pragma unroll
    for (int g = 0; g < 3; ++g) {
        const ulonglong2* src = reinterpret_cast<const ulonglong2*>(
            w_hh + (size_t)(g * H + j) * H + w * 32);
        #pragma unroll
        for (int i = 0; i < 8; ++i) {
            ulonglong2 q = src[i];
            wv[g][2 * i] = q.x; wv[g][2 * i + 1] = q.y;
        }
    }

    const bool lead = (w == 7);   // highest-wid warp wins issue arbitration
    float wir0=0,wir1=0,wiz0=0,wiz1=0,win0=0,win1=0,br=0,bz=0,bin=0,bhn=0;
    uint32_t rh[2][8], rb[2][8];
    const uint32_t mb0 = smem_u32(&s_mbar[0]);
    const uint32_t mb1 = smem_u32(&s_mbar[1]);
    if (lead) {
        wir0 = w_ih[(0*H+j)*2+0]; wir1 = w_ih[(0*H+j)*2+1];
        wiz0 = w_ih[(1*H+j)*2+0]; wiz1 = w_ih[(1*H+j)*2+1];
        win0 = w_ih[(2*H+j)*2+0]; win1 = w_ih[(2*H+j)*2+1];
        br  = b_ih[j] + b_hh[j];
        bz  = b_ih[H+j] + b_hh[H+j];
        bin = b_ih[2*H+j];
        bhn = b_hh[2*H+j];
        uint32_t lh0 = smem_u32(&sh_h[0][j]);
        uint32_t lh1 = smem_u32(&sh_h[1][j]);
        #pragma unroll
        for (int i = 0; i < 8; ++i) {
            uint32_t r = (rank + 1u + (uint32_t)i) & 7u;   // remotes first, self LAST
            rh[0][i] = mapa_u32(lh0, r); rh[1][i] = mapa_u32(lh1, r);
            rb[0][i] = mapa_u32(mb0, r); rb[1][i] = mapa_u32(mb1, r);
        }
    }

    for (int i = tid; i < 2 * H; i += NTHREADS) ((float*)sh_h)[i] = 0.0f;
    if (tid == 0) {
        MBARRIER_INIT(mb0, 1);
        MBARRIER_INIT(mb1, 1);
        MBARRIER_EXPECT_TX(mb1, 1024);   // step 1
        MBARRIER_EXPECT_TX(mb0, 1024);   // step 2
    }
    __syncthreads();
    CLUSTER_SYNC();

    const int ne = g_ne;
    unsigned par0 = 0, par1 = 0;
    float xc = 0, dc = 0, hprev = 0.0f;
    if (lead) { xc = g_ev_x[0]; dc = g_ev_dt[0]; }

    for (int e = 0; e < ne; ++e) {
        const int p = e & 1;
        const uint32_t mbp = p ? mb1 : mb0;
        float xn = 0, dn = 0, air = 0, aiz = 0, ain = 0;
        if (lead) {
            xn = g_ev_x[e + 1]; dn = g_ev_dt[e + 1];
            air = fmaf(wir1, dc, fmaf(wir0, xc, br));
            aiz = fmaf(wiz1, dc, fmaf(wiz0, xc, bz));
            ain = fmaf(win1, dc, fmaf(win0, xc, bin));
        }

        if (e > 0) {
            MBARRIER_WAIT(mbp, p ? par1 : par0);
            if (p) par1 ^= 1; else par0 ^= 1;
        }

        const ulonglong2* hb = reinterpret_cast<const ulonglong2*>(&sh_h[p][w * 32]);
        unsigned long long a0 = 0, a1 = 0, a2 = 0;
        #pragma unroll
        for (int i = 0; i < 8; ++i) {
            ulonglong2 hv = hb[i];
            FMA2(a0, wv[0][2*i], hv.x);  FMA2(a0, wv[0][2*i+1], hv.y);
            FMA2(a1, wv[1][2*i], hv.x);  FMA2(a1, wv[1][2*i+1], hv.y);
            FMA2(a2, wv[2][2*i], hv.x);  FMA2(a2, wv[2][2*i+1], hv.y);
        }
        float p0 = __uint_as_float((unsigned)a0) + __uint_as_float((unsigned)(a0 >> 32));
        float p1 = __uint_as_float((unsigned)a1) + __uint_as_float((unsigned)(a1 >> 32));
        float p2 = __uint_as_float((unsigned)a2) + __uint_as_float((unsigned)(a2 >> 32));
        if (lead) {   // pre-bias: fold x-terms/biases into lead's own partial
            p0 += air; p1 += aiz; p2 += bhn;
        }
        s_red[0][l][slot] = p0;
        s_red[1][l][slot] = p1;
        s_red[2][l][slot] = p2;

        // rearm for e+2, now AFTER the FMA/STS (off the wake->FMA path; still
        // before this warp's bar arrival => before any phase-(e+2) arrival)
        if (e > 0 && tid == 0) MBARRIER_EXPECT_TX(mbp, 1024);

        if (lead) {
            BAR_SYNC(1, NTHREADS);    // lead waits for all 8 warps' STS

            float4 r0 = *reinterpret_cast<const float4*>(&s_red[0][l][0]);
            float4 r1 = *reinterpret_cast<const float4*>(&s_red[0][l][4]);
            float4 z0 = *reinterpret_cast<const float4*>(&s_red[1][l][0]);
            float4 z1 = *reinterpret_cast<const float4*>(&s_red[1][l][4]);
            float4 n0 = *reinterpret_cast<const float4*>(&s_red[2][l][0]);
            float4 n1 = *reinterpret_cast<const float4*>(&s_red[2][l][4]);

            float s0 = ((r0.x + r0.y) + (r0.z + r0.w)) + ((r1.x + r1.y) + (r1.z + r1.w));
            float s1 = ((z0.x + z0.y) + (z0.z + z0.w)) + ((z1.x + z1.y) + (z1.z + z1.w));
            float tr = tanh_fast(0.5f * s0);
            float tz = tanh_fast(0.5f * s1);

            float s2 = ((n0.x + n0.y) + (n0.z + n0.w)) + ((n1.x + n1.y) + (n1.z + n1.w));
            float rg = fmaf(0.5f, tr, 0.5f);
            float ng = tanh_fast(fmaf(rg, s2, ain));   // s2 already has +bhn
            float zg = fmaf(0.5f, tz, 0.5f);
            float hnew = fmaf(zg, hprev - ng, ng);
            hprev = hnew;

            if (e + 1 < ne) {
                const int pn = p ^ 1;
                uint32_t v = __float_as_uint(hnew);
                #pragma unroll
                for (int i = 0; i < 8; ++i) ST_ASYNC_B32(rh[pn][i], v, rb[pn][i]);
            }
            g_hhist[(size_t)e * H + j] = hnew;
            xc = xn; dc = dn;
        } else {
            BAR_ARRIVE(1, NTHREADS);  // non-blocking: fall through to next wait
        }
    }
    CLUSTER_SYNC();
}

// ---- Pass 3a: pred per event (one warp per event) ---------------------------
__global__ void k_pred(const float* __restrict__ w_fc, const float* __restrict__ b_fc) {
    int e = blockIdx.x * 8 + (threadIdx.x >> 5);
    int l = threadIdx.x & 31;
    if (e >= g_ne) return;
    const float4* hr = reinterpret_cast<const float4*>(g_hhist + (size_t)e * H);
    const float4* wf = reinterpret_cast<const float4*>(w_fc);
    float4 h0 = hr[2*l], h1 = hr[2*l+1];
    float4 w0 = __ldg(&wf[2*l]), w1 = __ldg(&wf[2*l+1]);
    float s = h0.x*w0.x + h0.y*w0.y + h0.z*w0.z + h0.w*w0.w
            + h1.x*w1.x + h1.y*w1.y + h1.z*w1.z + h1.w*w1.w;
    #pragma unroll
    for (int o = 16; o > 0; o >>= 1) s += __shfl_xor_sync(0xffffffffu, s, o);
    if (l == 0) g_pred[e] = s + __ldg(b_fc);
}

// ---- Pass 3b: assemble [preds(T) | n_events | idx_padded(T)] ----------------
__global__ void k_out(float* __restrict__ out, int T, int out_size) {
    int t = blockIdx.x * blockDim.x + threadIdx.x;
    if (t >= T) return;
    int ne = g_ne;
    if (t < out_size) {
        int m = g_evmap[t];
        out[t] = (m >= 0) ? g_pred[m] : g_pred[0];
    }
    if (t == 0 && T < out_size) out[T] = (float)ne;
    int k = T + 1 + t;
    if (k < out_size) out[k] = (t < ne) ? (float)g_ev_t[t] : (float)T;
}

extern "C" void kernel_launch(void* const* d_in, const int* in_sizes, int n_in,
                              void* d_out, int out_size) {
    const float* x    = (const float*)d_in[0];
    const float* w_ih = (const float*)d_in[1];
    const float* w_hh = (const float*)d_in[2];
    const float* b_ih = (const float*)d_in[3];
    const float* b_hh = (const float*)d_in[4];
    const float* w_fc = (const float*)d_in[5];
    const float* b_fc = (const float*)d_in[6];
    int T = in_sizes[0];
    if (T > T_MAX) T = T_MAX;
    k_scan<<<1, 32>>>(x, T);
    k_main<<<8, NTHREADS>>>(w_ih, w_hh, b_ih, b_hh);
    k_pred<<<(T + 7) / 8, 256>>>(w_fc, b_fc);
    k_out<<<(T + 255) / 256, 256>>>((float*)d_out, T, out_size);
}

// round 13
// speedup vs baseline: 1.0943x; 1.0943x over previous
#include <cuda_runtime.h>
#include <cstdint>

#define T_MAX 32768
#define H 256
#define NTHREADS 256
#define THRESH 0.12f

__device__ float g_ev_x[T_MAX + 8];
__device__ float g_ev_dt[T_MAX + 8];
__device__ int   g_ev_t[T_MAX + 8];
__device__ int   g_evmap[T_MAX];
__device__ int   g_ne;
__device__ float g_hhist[(size_t)T_MAX * H];
__device__ float g_pred[T_MAX + 8];

__device__ __forceinline__ uint32_t smem_u32(const void* p) {
    uint32_t a;
    asm("{ .reg .u64 t; cvta.to.shared.u64 t, %1; cvt.u32.u64 %0, t; }" : "=r"(a) : "l"(p));
    return a;
}
__device__ __forceinline__ uint32_t mapa_u32(uint32_t laddr, uint32_t rank) {
    uint32_t r;
    asm("mapa.shared::cluster.u32 %0, %1, %2;" : "=r"(r) : "r"(laddr), "r"(rank));
    return r;
}
__device__ __forceinline__ uint32_t my_ctarank() {
    uint32_t r; asm("mov.u32 %0, %%cluster_ctarank;" : "=r"(r)); return r;
}
__device__ __forceinline__ float tanh_fast(float x) {
    float r; asm("tanh.approx.f32 %0, %1;" : "=f"(r) : "f"(x)); return r;
}

#define MBARRIER_INIT(addr, cnt) \
    asm volatile("mbarrier.init.shared.b64 [%0], %1;" :: "r"(addr), "r"((uint32_t)(cnt)) : "memory")
#define MBARRIER_EXPECT_TX(addr, tx) \
    asm volatile("mbarrier.arrive.expect_tx.shared.b64 _, [%0], %1;" :: "r"(addr), "r"((uint32_t)(tx)) : "memory")
#define MBARRIER_WAIT(mb, ph) do {                                                   \
    uint32_t _m = (mb), _p = (ph);                                                   \
    asm volatile("{ .reg .pred P1;\n"                                                \
        "WL_%=: mbarrier.try_wait.parity.acquire.cluster.shared::cta.b64 P1, [%0], %1, 0x989680;\n" \
        " @P1 bra.uni WD_%=;\n bra.uni WL_%=;\nWD_%=: }"                              \
        :: "r"(_m), "r"(_p) : "memory");                                             \
} while (0)
#define ST_ASYNC_B32(raddr, v, rmbar) \
    asm volatile("st.async.shared::cluster.mbarrier::complete_tx::bytes.b32 [%0], %1, [%2];" \
                 :: "r"(raddr), "r"(v), "r"(rmbar) : "memory")
#define CLUSTER_SYNC() do {                                       \
    asm volatile("barrier.cluster.arrive.aligned;" ::: "memory"); \
    asm volatile("barrier.cluster.wait.aligned;" ::: "memory");   \
} while (0)
#define FMA2(acc, a, b) asm("fma.rn.f32x2 %0, %1, %2, %0;" : "+l"(acc) : "l"(a), "l"(b))

// ---- Pass 1: exact sequential event scan -----------------------------------
__global__ void k_scan(const float* __restrict__ x, int T) {
    if (threadIdx.x != 0) return;
    float last_val = x[0] + 1.24f;   // (float)(2*0.12 + 1.0)
    float last_t = 0.0f;
    int ne = 0;
    const float4* x4 = reinterpret_cast<const float4*>(x);
    int t = 0;
    for (int b = 0; b < T / 4; ++b) {
        float4 v = __ldg(&x4[b]);
        float xs[4] = {v.x, v.y, v.z, v.w};
        #pragma unroll
        for (int i = 0; i < 4; ++i) {
            float xt = xs[i];
            if (fabsf(xt - last_val) >= THRESH) {
                g_ev_x[ne]  = xt;
                g_ev_dt[ne] = ((float)t - last_t) / 100.0f;
                g_ev_t[ne]  = t;
                last_val = xt; last_t = (float)t;
                ++ne;
            }
            g_evmap[t] = ne - 1;
            ++t;
        }
    }
    g_ne = ne;
    for (int i = 0; i < 8; ++i) { g_ev_x[ne + i] = 0.f; g_ev_dt[ne + i] = 0.f; }
}

// ---- Pass 2: 8-CTA cluster GRU (R9 champion + remotes-first send order) -----
__global__ void __cluster_dims__(8, 1, 1) __launch_bounds__(NTHREADS, 1)
k_main(const float* __restrict__ w_ih, const float* __restrict__ w_hh,
       const float* __restrict__ b_ih, const float* __restrict__ b_hh)
{
    __shared__ __align__(16) float sh_h[2][H];
    __shared__ __align__(16) float s_red[3][32][12];   // [gate][lane][slot]
    __shared__ __align__(8) unsigned long long s_mbar[2];

    const int tid = threadIdx.x;
    const int w   = tid >> 5;
    const int l   = tid & 31;
    // XOR-swizzled slot: conflict-free STS (R9 win)
    const int slot = w ^ ((l >> 2) & 7);
    const uint32_t rank = my_ctarank();
    const int j = (int)rank * 32 + l;

    // register-resident w_hh rows {j, H+j, 2H+j}, cols [32w, 32w+32)
    unsigned long long wv[3][16];
    #pragma unroll
    for (int g = 0; g < 3; ++g) {
        const ulonglong2* src = reinterpret_cast<const ulonglong2*>(
            w_hh + (size_t)(g * H + j) * H + w * 32);
        #pragma unroll
        for (int i = 0; i < 8; ++i) {
            ulonglong2 q = src[i];
            wv[g][2 * i] = q.x; wv[g][2 * i + 1] = q.y;
        }
    }

    const bool lead = (w == 0);
    float wir0=0,wir1=0,wiz0=0,wiz1=0,win0=0,win1=0,br=0,bz=0,bin=0,bhn=0;
    uint32_t rh[2][8], rb[2][8];
    const uint32_t mb0 = smem_u32(&s_mbar[0]);
    const uint32_t mb1 = smem_u32(&s_mbar[1]);
    if (lead) {
        wir0 = w_ih[(0*H+j)*2+0]; wir1 = w_ih[(0*H+j)*2+1];
        wiz0 = w_ih[(1*H+j)*2+0]; wiz1 = w_ih[(1*H+j)*2+1];
        win0 = w_ih[(2*H+j)*2+0]; win1 = w_ih[(2*H+j)*2+1];
        br  = b_ih[j] + b_hh[j];
        bz  = b_ih[H+j] + b_hh[H+j];
        bin = b_ih[2*H+j];
        bhn = b_hh[2*H+j];
        uint32_t lh0 = smem_u32(&sh_h[0][j]);
        uint32_t lh1 = smem_u32(&sh_h[1][j]);
        #pragma unroll
        for (int i = 0; i < 8; ++i) {
            uint32_t r = (rank + 1u + (uint32_t)i) & 7u;   // remotes first, self LAST
            rh[0][i] = mapa_u32(lh0, r); rh[1][i] = mapa_u32(lh1, r);
            rb[0][i] = mapa_u32(mb0, r); rb[1][i] = mapa_u32(mb1, r);
        }
    }

    for (int i = tid; i < 2 * H; i += NTHREADS) ((float*)sh_h)[i] = 0.0f;
    if (tid == 0) {
        MBARRIER_INIT(mb0, 1);
        MBARRIER_INIT(mb1, 1);
        MBARRIER_EXPECT_TX(mb1, 1024);   // step 1
        MBARRIER_EXPECT_TX(mb0, 1024);   // step 2
    }
    __syncthreads();
    CLUSTER_SYNC();

    const int ne = g_ne;
    unsigned par0 = 0, par1 = 0;
    float xc = 0, dc = 0, hprev = 0.0f;
    if (lead) { xc = g_ev_x[0]; dc = g_ev_dt[0]; }

    for (int e = 0; e < ne; ++e) {
        const int p = e & 1;
        const uint32_t mbp = p ? mb1 : mb0;
        float xn = 0, dn = 0, air = 0, aiz = 0, ain = 0;
        if (lead) {
            xn = g_ev_x[e + 1]; dn = g_ev_dt[e + 1];
            air = fmaf(wir1, dc, fmaf(wir0, xc, br));
            aiz = fmaf(wiz1, dc, fmaf(wiz0, xc, bz));
            ain = fmaf(win1, dc, fmaf(win0, xc, bin));
        }

        if (e > 0) {
            MBARRIER_WAIT(mbp, p ? par1 : par0);
            if (p) par1 ^= 1; else par0 ^= 1;
            if (tid == 255) MBARRIER_EXPECT_TX(mbp, 1024);   // rearm e+2
        }

        const ulonglong2* hb = reinterpret_cast<const ulonglong2*>(&sh_h[p][w * 32]);
        unsigned long long a0 = 0, a1 = 0, a2 = 0;
        #pragma unroll
        for (int i = 0; i < 8; ++i) {
            ulonglong2 hv = hb[i];
            FMA2(a0, wv[0][2*i], hv.x);  FMA2(a0, wv[0][2*i+1], hv.y);
            FMA2(a1, wv[1][2*i], hv.x);  FMA2(a1, wv[1][2*i+1], hv.y);
            FMA2(a2, wv[2][2*i], hv.x);  FMA2(a2, wv[2][2*i+1], hv.y);
        }
        s_red[0][l][slot] = __uint_as_float((unsigned)a0) + __uint_as_float((unsigned)(a0 >> 32));
        s_red[1][l][slot] = __uint_as_float((unsigned)a1) + __uint_as_float((unsigned)(a1 >> 32));
        s_red[2][l][slot] = __uint_as_float((unsigned)a2) + __uint_as_float((unsigned)(a2 >> 32));
        __syncthreads();

        if (lead) {
            // r-gate sum first: start its tanh (head of the serial rg->ng chain)
            float4 r0 = *reinterpret_cast<const float4*>(&s_red[0][l][0]);
            float4 r1 = *reinterpret_cast<const float4*>(&s_red[0][l][4]);
            float s0 = ((r0.x + r0.y) + (r0.z + r0.w)) + ((r1.x + r1.y) + (r1.z + r1.w));
            float tr = tanh_fast(0.5f * (s0 + air));

            float4 n0 = *reinterpret_cast<const float4*>(&s_red[2][l][0]);
            float4 n1 = *reinterpret_cast<const float4*>(&s_red[2][l][4]);
            float s2 = ((n0.x + n0.y) + (n0.z + n0.w)) + ((n1.x + n1.y) + (n1.z + n1.w));
            float hn = s2 + bhn;

            float4 z0 = *reinterpret_cast<const float4*>(&s_red[1][l][0]);
            float4 z1 = *reinterpret_cast<const float4*>(&s_red[1][l][4]);
            float s1 = ((z0.x + z0.y) + (z0.z + z0.w)) + ((z1.x + z1.y) + (z1.z + z1.w));

            float rg = fmaf(0.5f, tr, 0.5f);
            float ng = tanh_fast(fmaf(rg, hn, ain));
            float zg = fmaf(0.5f, tanh_fast(0.5f * (s1 + aiz)), 0.5f);
            float hnew = fmaf(zg, hprev - ng, ng);   // hp kept in register
            hprev = hnew;

            if (e + 1 < ne) {
                const int pn = p ^ 1;
                uint32_t v = __float_as_uint(hnew);
                #pragma unroll
                for (int i = 0; i < 8; ++i) ST_ASYNC_B32(rh[pn][i], v, rb[pn][i]);
            }
            g_hhist[(size_t)e * H + j] = hnew;
            xc = xn; dc = dn;
        }
    }
    CLUSTER_SYNC();
}

// ---- Pass 3a: pred per event (one warp per event) ---------------------------
__global__ void k_pred(const float* __restrict__ w_fc, const float* __restrict__ b_fc) {
    int e = blockIdx.x * 8 + (threadIdx.x >> 5);
    int l = threadIdx.x & 31;
    if (e >= g_ne) return;
    const float4* hr = reinterpret_cast<const float4*>(g_hhist + (size_t)e * H);
    const float4* wf = reinterpret_cast<const float4*>(w_fc);
    float4 h0 = hr[2*l], h1 = hr[2*l+1];
    float4 w0 = __ldg(&wf[2*l]), w1 = __ldg(&wf[2*l+1]);
    float s = h0.x*w0.x + h0.y*w0.y + h0.z*w0.z + h0.w*w0.w
            + h1.x*w1.x + h1.y*w1.y + h1.z*w1.z + h1.w*w1.w;
    #pragma unroll
    for (int o = 16; o > 0; o >>= 1) s += __shfl_xor_sync(0xffffffffu, s, o);
    if (l == 0) g_pred[e] = s + __ldg(b_fc);
}

// ---- Pass 3b: assemble [preds(T) | n_events | idx_padded(T)] ----------------
__global__ void k_out(float* __restrict__ out, int T, int out_size) {
    int t = blockIdx.x * blockDim.x + threadIdx.x;
    if (t >= T) return;
    int ne = g_ne;
    if (t < out_size) {
        int m = g_evmap[t];
        out[t] = (m >= 0) ? g_pred[m] : g_pred[0];
    }
    if (t == 0 && T < out_size) out[T] = (float)ne;
    int k = T + 1 + t;
    if (k < out_size) out[k] = (t < ne) ? (float)g_ev_t[t] : (float)T;
}

extern "C" void kernel_launch(void* const* d_in, const int* in_sizes, int n_in,
                              void* d_out, int out_size) {
    const float* x    = (const float*)d_in[0];
    const float* w_ih = (const float*)d_in[1];
    const float* w_hh = (const float*)d_in[2];
    const float* b_ih = (const float*)d_in[3];
    const float* b_hh = (const float*)d_in[4];
    const float* w_fc = (const float*)d_in[5];
    const float* b_fc = (const float*)d_in[6];
    int T = in_sizes[0];
    if (T > T_MAX) T = T_MAX;
    k_scan<<<1, 32>>>(x, T);
    k_main<<<8, NTHREADS>>>(w_ih, w_hh, b_ih, b_hh);
    k_pred<<<(T + 7) / 8, 256>>>(w_fc, b_fc);
    k_out<<<(T + 255) / 256, 256>>>((float*)d_out, T, out_size);
}

// round 14
// speedup vs baseline: 1.0964x; 1.0019x over previous
#include <cuda_runtime.h>
#include <cstdint>

#define T_MAX 32768
#define H 256
#define NTHREADS 256
#define THRESH 0.12f

__device__ float g_ev_x[T_MAX + 8];
__device__ float g_ev_dt[T_MAX + 8];
__device__ int   g_ev_t[T_MAX + 8];
__device__ int   g_evmap[T_MAX];
__device__ int   g_ne;
__device__ float g_hhist[(size_t)T_MAX * H];
__device__ float g_pred[T_MAX + 8];

__device__ __forceinline__ uint32_t smem_u32(const void* p) {
    uint32_t a;
    asm("{ .reg .u64 t; cvta.to.shared.u64 t, %1; cvt.u32.u64 %0, t; }" : "=r"(a) : "l"(p));
    return a;
}
__device__ __forceinline__ uint32_t mapa_u32(uint32_t laddr, uint32_t rank) {
    uint32_t r;
    asm("mapa.shared::cluster.u32 %0, %1, %2;" : "=r"(r) : "r"(laddr), "r"(rank));
    return r;
}
__device__ __forceinline__ uint32_t my_ctarank() {
    uint32_t r; asm("mov.u32 %0, %%cluster_ctarank;" : "=r"(r)); return r;
}
__device__ __forceinline__ float tanh_fast(float x) {
    float r; asm("tanh.approx.f32 %0, %1;" : "=f"(r) : "f"(x)); return r;
}

#define MBARRIER_INIT(addr, cnt) \
    asm volatile("mbarrier.init.shared.b64 [%0], %1;" :: "r"(addr), "r"((uint32_t)(cnt)) : "memory")
#define MBARRIER_EXPECT_TX(addr, tx) \
    asm volatile("mbarrier.arrive.expect_tx.shared.b64 _, [%0], %1;" :: "r"(addr), "r"((uint32_t)(tx)) : "memory")
// CTA-scope acquire (canonical TMA-style consumption): st.async data is made
// visible at OUR barrier by tx-complete; consumers are all in-CTA.
#define MBARRIER_WAIT(mb, ph) do {                                                   \
    uint32_t _m = (mb), _p = (ph);                                                   \
    asm volatile("{ .reg .pred P1;\n"                                                \
        "WL_%=: mbarrier.try_wait.parity.acquire.cta.shared::cta.b64 P1, [%0], %1, 0x989680;\n" \
        " @P1 bra.uni WD_%=;\n bra.uni WL_%=;\nWD_%=: }"                              \
        :: "r"(_m), "r"(_p) : "memory");                                             \
} while (0)
#define ST_ASYNC_B32(raddr, v, rmbar) \
    asm volatile("st.async.shared::cluster.mbarrier::complete_tx::bytes.b32 [%0], %1, [%2];" \
                 :: "r"(raddr), "r"(v), "r"(rmbar) : "memory")
#define CLUSTER_SYNC() do {                                       \
    asm volatile("barrier.cluster.arrive.aligned;" ::: "memory"); \
    asm volatile("barrier.cluster.wait.aligned;" ::: "memory");   \
} while (0)
#define FMA2(acc, a, b) asm("fma.rn.f32x2 %0, %1, %2, %0;" : "+l"(acc) : "l"(a), "l"(b))

// ---- Pass 1: exact sequential event scan -----------------------------------
__global__ void k_scan(const float* __restrict__ x, int T) {
    if (threadIdx.x != 0) return;
    float last_val = x[0] + 1.24f;   // (float)(2*0.12 + 1.0)
    float last_t = 0.0f;
    int ne = 0;
    const float4* x4 = reinterpret_cast<const float4*>(x);
    int t = 0;
    for (int b = 0; b < T / 4; ++b) {
        float4 v = __ldg(&x4[b]);
        float xs[4] = {v.x, v.y, v.z, v.w};
        #pragma unroll
        for (int i = 0; i < 4; ++i) {
            float xt = xs[i];
            if (fabsf(xt - last_val) >= THRESH) {
                g_ev_x[ne]  = xt;
                g_ev_dt[ne] = ((float)t - last_t) / 100.0f;
                g_ev_t[ne]  = t;
                last_val = xt; last_t = (float)t;
                ++ne;
            }
            g_evmap[t] = ne - 1;
            ++t;
        }
    }
    g_ne = ne;
    for (int i = 0; i < 8; ++i) { g_ev_x[ne + i] = 0.f; g_ev_dt[ne + i] = 0.f; }
}

// ---- Pass 2: 8-CTA cluster GRU (R9 champion + cta-scope acquire) ------------
__global__ void __cluster_dims__(8, 1, 1) __launch_bounds__(NTHREADS, 1)
k_main(const float* __restrict__ w_ih, const float* __restrict__ w_hh,
       const float* __restrict__ b_ih, const float* __restrict__ b_hh)
{
    __shared__ __align__(16) float sh_h[2][H];
    __shared__ __align__(16) float s_red[3][32][12];   // [gate][lane][slot]
    __shared__ __align__(8) unsigned long long s_mbar[2];

    const int tid = threadIdx.x;
    const int w   = tid >> 5;
    const int l   = tid & 31;
    // XOR-swizzled slot: conflict-free STS (R9 win)
    const int slot = w ^ ((l >> 2) & 7);
    const uint32_t rank = my_ctarank();
    const int j = (int)rank * 32 + l;

    // register-resident w_hh rows {j, H+j, 2H+j}, cols [32w, 32w+32)
    unsigned long long wv[3][16];
    #pragma unroll
    for (int g = 0; g < 3; ++g) {
        const ulonglong2* src = reinterpret_cast<const ulonglong2*>(
            w_hh + (size_t)(g * H + j) * H + w * 32);
        #pragma unroll
        for (int i = 0; i < 8; ++i) {
            ulonglong2 q = src[i];
            wv[g][2 * i] = q.x; wv[g][2 * i + 1] = q.y;
        }
    }

    const bool lead = (w == 0);
    float wir0=0,wir1=0,wiz0=0,wiz1=0,win0=0,win1=0,br=0,bz=0,bin=0,bhn=0;
    uint32_t rh[2][8], rb[2][8];
    const uint32_t mb0 = smem_u32(&s_mbar[0]);
    const uint32_t mb1 = smem_u32(&s_mbar[1]);
    if (lead) {
        wir0 = w_ih[(0*H+j)*2+0]; wir1 = w_ih[(0*H+j)*2+1];
        wiz0 = w_ih[(1*H+j)*2+0]; wiz1 = w_ih[(1*H+j)*2+1];
        win0 = w_ih[(2*H+j)*2+0]; win1 = w_ih[(2*H+j)*2+1];
        br  = b_ih[j] + b_hh[j];
        bz  = b_ih[H+j] + b_hh[H+j];
        bin = b_ih[2*H+j];
        bhn = b_hh[2*H+j];
        uint32_t lh0 = smem_u32(&sh_h[0][j]);
        uint32_t lh1 = smem_u32(&sh_h[1][j]);
        #pragma unroll
        for (int i = 0; i < 8; ++i) {
            uint32_t r = (rank + (uint32_t)i) & 7u;   // champion rotation (self first)
            rh[0][i] = mapa_u32(lh0, r); rh[1][i] = mapa_u32(lh1, r);
            rb[0][i] = mapa_u32(mb0, r); rb[1][i] = mapa_u32(mb1, r);
        }
    }

    for (int i = tid; i < 2 * H; i += NTHREADS) ((float*)sh_h)[i] = 0.0f;
    if (tid == 0) {
        MBARRIER_INIT(mb0, 1);
        MBARRIER_INIT(mb1, 1);
        MBARRIER_EXPECT_TX(mb1, 1024);   // step 1
        MBARRIER_EXPECT_TX(mb0, 1024);   // step 2
    }
    __syncthreads();
    CLUSTER_SYNC();

    const int ne = g_ne;
    unsigned par0 = 0, par1 = 0;
    float xc = 0, dc = 0, hprev = 0.0f;
    if (lead) { xc = g_ev_x[0]; dc = g_ev_dt[0]; }

    for (int e = 0; e < ne; ++e) {
        const int p = e & 1;
        const uint32_t mbp = p ? mb1 : mb0;
        float xn = 0, dn = 0, air = 0, aiz = 0, ain = 0;
        if (lead) {
            xn = g_ev_x[e + 1]; dn = g_ev_dt[e + 1];
            air = fmaf(wir1, dc, fmaf(wir0, xc, br));
            aiz = fmaf(wiz1, dc, fmaf(wiz0, xc, bz));
            ain = fmaf(win1, dc, fmaf(win0, xc, bin));
        }

        if (e > 0) {
            MBARRIER_WAIT(mbp, p ? par1 : par0);
            if (p) par1 ^= 1; else par0 ^= 1;
            if (tid == 255) MBARRIER_EXPECT_TX(mbp, 1024);   // rearm e+2
        }

        const ulonglong2* hb = reinterpret_cast<const ulonglong2*>(&sh_h[p][w * 32]);
        unsigned long long a0 = 0, a1 = 0, a2 = 0;
        #pragma unroll
        for (int i = 0; i < 8; ++i) {
            ulonglong2 hv = hb[i];
            FMA2(a0, wv[0][2*i], hv.x);  FMA2(a0, wv[0][2*i+1], hv.y);
            FMA2(a1, wv[1][2*i], hv.x);  FMA2(a1, wv[1][2*i+1], hv.y);
            FMA2(a2, wv[2][2*i], hv.x);  FMA2(a2, wv[2][2*i+1], hv.y);
        }
        s_red[0][l][slot] = __uint_as_float((unsigned)a0) + __uint_as_float((unsigned)(a0 >> 32));
        s_red[1][l][slot] = __uint_as_float((unsigned)a1) + __uint_as_float((unsigned)(a1 >> 32));
        s_red[2][l][slot] = __uint_as_float((unsigned)a2) + __uint_as_float((unsigned)(a2 >> 32));
        __syncthreads();

        if (lead) {
            // r-gate sum first: start its tanh (head of the serial rg->ng chain)
            float4 r0 = *reinterpret_cast<const float4*>(&s_red[0][l][0]);
            float4 r1 = *reinterpret_cast<const float4*>(&s_red[0][l][4]);
            float s0 = ((r0.x + r0.y) + (r0.z + r0.w)) + ((r1.x + r1.y) + (r1.z + r1.w));
            float tr = tanh_fast(0.5f * (s0 + air));

            float4 n0 = *reinterpret_cast<const float4*>(&s_red[2][l][0]);
            float4 n1 = *reinterpret_cast<const float4*>(&s_red[2][l][4]);
            float s2 = ((n0.x + n0.y) + (n0.z + n0.w)) + ((n1.x + n1.y) + (n1.z + n1.w));
            float hn = s2 + bhn;

            float4 z0 = *reinterpret_cast<const float4*>(&s_red[1][l][0]);
            float4 z1 = *reinterpret_cast<const float4*>(&s_red[1][l][4]);
            float s1 = ((z0.x + z0.y) + (z0.z + z0.w)) + ((z1.x + z1.y) + (z1.z + z1.w));

            float rg = fmaf(0.5f, tr, 0.5f);
            float ng = tanh_fast(fmaf(rg, hn, ain));
            float zg = fmaf(0.5f, tanh_fast(0.5f * (s1 + aiz)), 0.5f);
            float hnew = fmaf(zg, hprev - ng, ng);   // hp kept in register
            hprev = hnew;

            if (e + 1 < ne) {
                const int pn = p ^ 1;
                uint32_t v = __float_as_uint(hnew);
                #pragma unroll
                for (int i = 0; i < 8; ++i) ST_ASYNC_B32(rh[pn][i], v, rb[pn][i]);
            }
            g_hhist[(size_t)e * H + j] = hnew;
            xc = xn; dc = dn;
        }
    }
    CLUSTER_SYNC();
}

// ---- Pass 3a: pred per event (one warp per event) ---------------------------
__global__ void k_pred(const float* __restrict__ w_fc, const float* __restrict__ b_fc) {
    int e = blockIdx.x * 8 + (threadIdx.x >> 5);
    int l = threadIdx.x & 31;
    if (e >= g_ne) return;
    const float4* hr = reinterpret_cast<const float4*>(g_hhist + (size_t)e * H);
    const float4* wf = reinterpret_cast<const float4*>(w_fc);
    float4 h0 = hr[2*l], h1 = hr[2*l+1];
    float4 w0 = __ldg(&wf[2*l]), w1 = __ldg(&wf[2*l+1]);
    float s = h0.x*w0.x + h0.y*w0.y + h0.z*w0.z + h0.w*w0.w
            + h1.x*w1.x + h1.y*w1.y + h1.z*w1.z + h1.w*w1.w;
    #pragma unroll
    for (int o = 16; o > 0; o >>= 1) s += __shfl_xor_sync(0xffffffffu, s, o);
    if (l == 0) g_pred[e] = s + __ldg(b_fc);
}

// ---- Pass 3b: assemble [preds(T) | n_events | idx_padded(T)] ----------------
__global__ void k_out(float* __restrict__ out, int T, int out_size) {
    int t = blockIdx.x * blockDim.x + threadIdx.x;
    if (t >= T) return;
    int ne = g_ne;
    if (t < out_size) {
        int m = g_evmap[t];
        out[t] = (m >= 0) ? g_pred[m] : g_pred[0];
    }
    if (t == 0 && T < out_size) out[T] = (float)ne;
    int k = T + 1 + t;
    if (k < out_size) out[k] = (t < ne) ? (float)g_ev_t[t] : (float)T;
}

extern "C" void kernel_launch(void* const* d_in, const int* in_sizes, int n_in,
                              void* d_out, int out_size) {
    const float* x    = (const float*)d_in[0];
    const float* w_ih = (const float*)d_in[1];
    const float* w_hh = (const float*)d_in[2];
    const float* b_ih = (const float*)d_in[3];
    const float* b_hh = (const float*)d_in[4];
    const float* w_fc = (const float*)d_in[5];
    const float* b_fc = (const float*)d_in[6];
    int T = in_sizes[0];
    if (T > T_MAX) T = T_MAX;
    k_scan<<<1, 32>>>(x, T);
    k_main<<<8, NTHREADS>>>(w_ih, w_hh, b_ih, b_hh);
    k_pred<<<(T + 7) / 8, 256>>>(w_fc, b_fc);
    k_out<<<(T + 255) / 256, 256>>>((float*)d_out, T, out_size);
}

// round 15
// speedup vs baseline: 1.1937x; 1.0888x over previous
#include <cuda_runtime.h>
#include <cstdint>

#define T_MAX 32768
#define H 256
#define NTHREADS 256
#define THRESH 0.12f

__device__ float g_ev_x[T_MAX + 8];
__device__ float g_ev_dt[T_MAX + 8];
__device__ int   g_ev_t[T_MAX + 8];
__device__ int   g_evmap[T_MAX];
__device__ int   g_ne;
__device__ float g_hhist[(size_t)T_MAX * H];
__device__ float g_pred[T_MAX + 8];

__device__ __forceinline__ uint32_t smem_u32(const void* p) {
    uint32_t a;
    asm("{ .reg .u64 t; cvta.to.shared.u64 t, %1; cvt.u32.u64 %0, t; }" : "=r"(a) : "l"(p));
    return a;
}
__device__ __forceinline__ uint32_t mapa_u32(uint32_t laddr, uint32_t rank) {
    uint32_t r;
    asm("mapa.shared::cluster.u32 %0, %1, %2;" : "=r"(r) : "r"(laddr), "r"(rank));
    return r;
}
__device__ __forceinline__ uint32_t my_ctarank() {
    uint32_t r; asm("mov.u32 %0, %%cluster_ctarank;" : "=r"(r)); return r;
}
__device__ __forceinline__ float tanh_fast(float x) {
    float r; asm("tanh.approx.f32 %0, %1;" : "=f"(r) : "f"(x)); return r;
}

#define MBARRIER_INIT(addr, cnt) \
    asm volatile("mbarrier.init.shared.b64 [%0], %1;" :: "r"(addr), "r"((uint32_t)(cnt)) : "memory")
#define MBARRIER_EXPECT_TX(addr, tx) \
    asm volatile("mbarrier.arrive.expect_tx.shared.b64 _, [%0], %1;" :: "r"(addr), "r"((uint32_t)(tx)) : "memory")
#define MBARRIER_WAIT(mb, ph) do {                                                   \
    uint32_t _m = (mb), _p = (ph);                                                   \
    asm volatile("{ .reg .pred P1;\n"                                                \
        "WL_%=: mbarrier.try_wait.parity.acquire.cluster.shared::cta.b64 P1, [%0], %1, 0x989680;\n" \
        " @P1 bra.uni WD_%=;\n bra.uni WL_%=;\nWD_%=: }"                              \
        :: "r"(_m), "r"(_p) : "memory");                                             \
} while (0)
#define ST_ASYNC_B32(raddr, v, rmbar) \
    asm volatile("st.async.shared::cluster.mbarrier::complete_tx::bytes.b32 [%0], %1, [%2];" \
                 :: "r"(raddr), "r"(v), "r"(rmbar) : "memory")
#define CLUSTER_SYNC() do {                                       \
    asm volatile("barrier.cluster.arrive.aligned;" ::: "memory"); \
    asm volatile("barrier.cluster.wait.aligned;" ::: "memory");   \
} while (0)
#define FMA2(acc, a, b) asm("fma.rn.f32x2 %0, %1, %2, %0;" : "+l"(acc) : "l"(a), "l"(b))

// ---- Pass 1: exact sequential event scan -----------------------------------
__global__ void k_scan(const float* __restrict__ x, int T) {
    if (threadIdx.x != 0) return;
    float last_val = x[0] + 1.24f;   // (float)(2*0.12 + 1.0)
    float last_t = 0.0f;
    int ne = 0;
    const float4* x4 = reinterpret_cast<const float4*>(x);
    int t = 0;
    for (int b = 0; b < T / 4; ++b) {
        float4 v = __ldg(&x4[b]);
        float xs[4] = {v.x, v.y, v.z, v.w};
        #pragma unroll
        for (int i = 0; i < 4; ++i) {
            float xt = xs[i];
            if (fabsf(xt - last_val) >= THRESH) {
                g_ev_x[ne]  = xt;
                g_ev_dt[ne] = ((float)t - last_t) / 100.0f;
                g_ev_t[ne]  = t;
                last_val = xt; last_t = (float)t;
                ++ne;
            }
            g_evmap[t] = ne - 1;
            ++t;
        }
    }
    g_ne = ne;
    for (int i = 0; i < 8; ++i) { g_ev_x[ne + i] = 0.f; g_ev_dt[ne + i] = 0.f; }
}

// ---- Pass 2: 8-CTA cluster GRU (R9 champion, event loop unrolled x2 with
//      compile-time phase specialization) ------------------------------------
__global__ void __cluster_dims__(8, 1, 1) __launch_bounds__(NTHREADS, 1)
k_main(const float* __restrict__ w_ih, const float* __restrict__ w_hh,
       const float* __restrict__ b_ih, const float* __restrict__ b_hh)
{
    __shared__ __align__(16) float sh_h[2][H];
    __shared__ __align__(16) float s_red[3][32][12];   // [gate][lane][slot]
    __shared__ __align__(8) unsigned long long s_mbar[2];

    const int tid = threadIdx.x;
    const int w   = tid >> 5;
    const int l   = tid & 31;
    // XOR-swizzled slot: conflict-free STS (R9 win)
    const int slot = w ^ ((l >> 2) & 7);
    const uint32_t rank = my_ctarank();
    const int j = (int)rank * 32 + l;

    // register-resident w_hh rows {j, H+j, 2H+j}, cols [32w, 32w+32)
    unsigned long long wv[3][16];
    #pragma unroll
    for (int g = 0; g < 3; ++g) {
        const ulonglong2* src = reinterpret_cast<const ulonglong2*>(
            w_hh + (size_t)(g * H + j) * H + w * 32);
        #pragma unroll
        for (int i = 0; i < 8; ++i) {
            ulonglong2 q = src[i];
            wv[g][2 * i] = q.x; wv[g][2 * i + 1] = q.y;
        }
    }

    const bool lead = (w == 0);
    float wir0=0,wir1=0,wiz0=0,wiz1=0,win0=0,win1=0,br=0,bz=0,bin=0,bhn=0;
    uint32_t rh[2][8], rb[2][8];
    const uint32_t mb0 = smem_u32(&s_mbar[0]);
    const uint32_t mb1 = smem_u32(&s_mbar[1]);
    if (lead) {
        wir0 = w_ih[(0*H+j)*2+0]; wir1 = w_ih[(0*H+j)*2+1];
        wiz0 = w_ih[(1*H+j)*2+0]; wiz1 = w_ih[(1*H+j)*2+1];
        win0 = w_ih[(2*H+j)*2+0]; win1 = w_ih[(2*H+j)*2+1];
        br  = b_ih[j] + b_hh[j];
        bz  = b_ih[H+j] + b_hh[H+j];
        bin = b_ih[2*H+j];
        bhn = b_hh[2*H+j];
        uint32_t lh0 = smem_u32(&sh_h[0][j]);
        uint32_t lh1 = smem_u32(&sh_h[1][j]);
        #pragma unroll
        for (int i = 0; i < 8; ++i) {
            uint32_t r = (rank + (uint32_t)i) & 7u;   // champion rotation (self first)
            rh[0][i] = mapa_u32(lh0, r); rh[1][i] = mapa_u32(lh1, r);
            rb[0][i] = mapa_u32(mb0, r); rb[1][i] = mapa_u32(mb1, r);
        }
    }

    for (int i = tid; i < 2 * H; i += NTHREADS) ((float*)sh_h)[i] = 0.0f;
    if (tid == 0) {
        MBARRIER_INIT(mb0, 1);
        MBARRIER_INIT(mb1, 1);
        MBARRIER_EXPECT_TX(mb1, 1024);   // step 1
        MBARRIER_EXPECT_TX(mb0, 1024);   // step 2
    }
    __syncthreads();
    CLUSTER_SYNC();

    const int ne = g_ne;
    unsigned par0 = 0, par1 = 0;
    float xc = 0, dc = 0, hprev = 0.0f;
    if (lead) { xc = g_ev_x[0]; dc = g_ev_dt[0]; }

// One event step with compile-time phase P (all phase selects fold away).
#define GRU_STEP(E, P, PARV, MBP)                                                   \
    do {                                                                            \
        const int e = (E);                                                          \
        float xn = 0, dn = 0, air = 0, aiz = 0, ain = 0;                            \
        if (lead) {                                                                 \
            xn = g_ev_x[e + 1]; dn = g_ev_dt[e + 1];                                \
            air = fmaf(wir1, dc, fmaf(wir0, xc, br));                               \
            aiz = fmaf(wiz1, dc, fmaf(wiz0, xc, bz));                               \
            ain = fmaf(win1, dc, fmaf(win0, xc, bin));                              \
        }                                                                           \
        if (e > 0) {                                                                \
            MBARRIER_WAIT((MBP), (PARV));                                           \
            (PARV) ^= 1;                                                            \
            if (tid == 255) MBARRIER_EXPECT_TX((MBP), 1024);   /* rearm e+2 */      \
        }                                                                           \
        const ulonglong2* hb = reinterpret_cast<const ulonglong2*>(&sh_h[P][w * 32]);\
        unsigned long long a0 = 0, a1 = 0, a2 = 0;                                  \
        _Pragma("unroll")                                                           \
        for (int i = 0; i < 8; ++i) {                                               \
            ulonglong2 hv = hb[i];                                                  \
            FMA2(a0, wv[0][2*i], hv.x);  FMA2(a0, wv[0][2*i+1], hv.y);              \
            FMA2(a1, wv[1][2*i], hv.x);  FMA2(a1, wv[1][2*i+1], hv.y);              \
            FMA2(a2, wv[2][2*i], hv.x);  FMA2(a2, wv[2][2*i+1], hv.y);              \
        }                                                                           \
        s_red[0][l][slot] = __uint_as_float((unsigned)a0) + __uint_as_float((unsigned)(a0 >> 32)); \
        s_red[1][l][slot] = __uint_as_float((unsigned)a1) + __uint_as_float((unsigned)(a1 >> 32)); \
        s_red[2][l][slot] = __uint_as_float((unsigned)a2) + __uint_as_float((unsigned)(a2 >> 32)); \
        __syncthreads();                                                            \
        if (lead) {                                                                 \
            float4 r0 = *reinterpret_cast<const float4*>(&s_red[0][l][0]);          \
            float4 r1 = *reinterpret_cast<const float4*>(&s_red[0][l][4]);          \
            float s0 = ((r0.x + r0.y) + (r0.z + r0.w)) + ((r1.x + r1.y) + (r1.z + r1.w)); \
            float tr = tanh_fast(0.5f * (s0 + air));                                \
            float4 n0 = *reinterpret_cast<const float4*>(&s_red[2][l][0]);          \
            float4 n1 = *reinterpret_cast<const float4*>(&s_red[2][l][4]);          \
            float s2 = ((n0.x + n0.y) + (n0.z + n0.w)) + ((n1.x + n1.y) + (n1.z + n1.w)); \
            float hn = s2 + bhn;                                                    \
            float4 z0 = *reinterpret_cast<const float4*>(&s_red[1][l][0]);          \
            float4 z1 = *reinterpret_cast<const float4*>(&s_red[1][l][4]);          \
            float s1 = ((z0.x + z0.y) + (z0.z + z0.w)) + ((z1.x + z1.y) + (z1.z + z1.w)); \
            float rg = fmaf(0.5f, tr, 0.5f);                                        \
            float ng = tanh_fast(fmaf(rg, hn, ain));                                \
            float zg = fmaf(0.5f, tanh_fast(0.5f * (s1 + aiz)), 0.5f);              \
            float hnew = fmaf(zg, hprev - ng, ng);                                  \
            hprev = hnew;                                                           \
            if (e + 1 < ne) {                                                       \
                uint32_t v = __float_as_uint(hnew);                                 \
                _Pragma("unroll")                                                   \
                for (int i = 0; i < 8; ++i)                                         \
                    ST_ASYNC_B32(rh[(P) ^ 1][i], v, rb[(P) ^ 1][i]);                \
            }                                                                       \
            g_hhist[(size_t)e * H + j] = hnew;                                      \
            xc = xn; dc = dn;                                                       \
        }                                                                           \
    } while (0)

    for (int e2 = 0; e2 < ne; e2 += 2) {
        GRU_STEP(e2, 0, par0, mb0);
        if (e2 + 1 < ne) GRU_STEP(e2 + 1, 1, par1, mb1);
    }
#undef GRU_STEP
    CLUSTER_SYNC();
}

// ---- Pass 3a: pred per event (one warp per event) ---------------------------
__global__ void k_pred(const float* __restrict__ w_fc, const float* __restrict__ b_fc) {
    int e = blockIdx.x * 8 + (threadIdx.x >> 5);
    int l = threadIdx.x & 31;
    if (e >= g_ne) return;
    const float4* hr = reinterpret_cast<const float4*>(g_hhist + (size_t)e * H);
    const float4* wf = reinterpret_cast<const float4*>(w_fc);
    float4 h0 = hr[2*l], h1 = hr[2*l+1];
    float4 w0 = __ldg(&wf[2*l]), w1 = __ldg(&wf[2*l+1]);
    float s = h0.x*w0.x + h0.y*w0.y + h0.z*w0.z + h0.w*w0.w
            + h1.x*w1.x + h1.y*w1.y + h1.z*w1.z + h1.w*w1.w;
    #pragma unroll
    for (int o = 16; o > 0; o >>= 1) s += __shfl_xor_sync(0xffffffffu, s, o);
    if (l == 0) g_pred[e] = s + __ldg(b_fc);
}

// ---- Pass 3b: assemble [preds(T) | n_events | idx_padded(T)] ----------------
__global__ void k_out(float* __restrict__ out, int T, int out_size) {
    int t = blockIdx.x * blockDim.x + threadIdx.x;
    if (t >= T) return;
    int ne = g_ne;
    if (t < out_size) {
        int m = g_evmap[t];
        out[t] = (m >= 0) ? g_pred[m] : g_pred[0];
    }
    if (t == 0 && T < out_size) out[T] = (float)ne;
    int k = T + 1 + t;
    if (k < out_size) out[k] = (t < ne) ? (float)g_ev_t[t] : (float)T;
}

extern "C" void kernel_launch(void* const* d_in, const int* in_sizes, int n_in,
                              void* d_out, int out_size) {
    const float* x    = (const float*)d_in[0];
    const float* w_ih = (const float*)d_in[1];
    const float* w_hh = (const float*)d_in[2];
    const float* b_ih = (const float*)d_in[3];
    const float* b_hh = (const float*)d_in[4];
    const float* w_fc = (const float*)d_in[5];
    const float* b_fc = (const float*)d_in[6];
    int T = in_sizes[0];
    if (T > T_MAX) T = T_MAX;
    k_scan<<<1, 32>>>(x, T);
    k_main<<<8, NTHREADS>>>(w_ih, w_hh, b_ih, b_hh);
    k_pred<<<(T + 7) / 8, 256>>>(w_fc, b_fc);
    k_out<<<(T + 255) / 256, 256>>>((float*)d_out, T, out_size);
}

// round 17
// speedup vs baseline: 1.1995x; 1.0048x over previous
#include <cuda_runtime.h>
#include <cstdint>

#define T_MAX 32768
#define H 256
#define NTHREADS 256
#define THRESH 0.12f

__device__ float g_ev_x[T_MAX + 8];
__device__ float g_ev_dt[T_MAX + 8];
__device__ int   g_ev_t[T_MAX + 8];
__device__ int   g_evmap[T_MAX];
__device__ int   g_ne;
__device__ float g_hhist[(size_t)T_MAX * H];
__device__ float g_pred[T_MAX + 8];

__device__ __forceinline__ uint32_t smem_u32(const void* p) {
    uint32_t a;
    asm("{ .reg .u64 t; cvta.to.shared.u64 t, %1; cvt.u32.u64 %0, t; }" : "=r"(a) : "l"(p));
    return a;
}
__device__ __forceinline__ uint32_t mapa_u32(uint32_t laddr, uint32_t rank) {
    uint32_t r;
    asm("mapa.shared::cluster.u32 %0, %1, %2;" : "=r"(r) : "r"(laddr), "r"(rank));
    return r;
}
__device__ __forceinline__ uint32_t my_ctarank() {
    uint32_t r; asm("mov.u32 %0, %%cluster_ctarank;" : "=r"(r)); return r;
}
__device__ __forceinline__ float tanh_fast(float x) {
    float r; asm("tanh.approx.f32 %0, %1;" : "=f"(r) : "f"(x)); return r;
}

#define MBARRIER_INIT(addr, cnt) \
    asm volatile("mbarrier.init.shared.b64 [%0], %1;" :: "r"(addr), "r"((uint32_t)(cnt)) : "memory")
#define MBARRIER_EXPECT_TX(addr, tx) \
    asm volatile("mbarrier.arrive.expect_tx.shared.b64 _, [%0], %1;" :: "r"(addr), "r"((uint32_t)(tx)) : "memory")
#define MBARRIER_WAIT(mb, ph) do {                                                   \
    uint32_t _m = (mb), _p = (ph);                                                   \
    asm volatile("{ .reg .pred P1;\n"                                                \
        "WL_%=: mbarrier.try_wait.parity.acquire.cluster.shared::cta.b64 P1, [%0], %1, 0x989680;\n" \
        " @P1 bra.uni WD_%=;\n bra.uni WL_%=;\nWD_%=: }"                              \
        :: "r"(_m), "r"(_p) : "memory");                                             \
} while (0)
#define ST_ASYNC_B32(raddr, v, rmbar) \
    asm volatile("st.async.shared::cluster.mbarrier::complete_tx::bytes.b32 [%0], %1, [%2];" \
                 :: "r"(raddr), "r"(v), "r"(rmbar) : "memory")
#define CLUSTER_SYNC() do {                                       \
    asm volatile("barrier.cluster.arrive.aligned;" ::: "memory"); \
    asm volatile("barrier.cluster.wait.aligned;" ::: "memory");   \
} while (0)
#define FMA2(acc, a, b) asm("fma.rn.f32x2 %0, %1, %2, %0;" : "+l"(acc) : "l"(a), "l"(b))

// ---- Pass 1: exact sequential event scan -----------------------------------
__global__ void k_scan(const float* __restrict__ x, int T) {
    if (threadIdx.x != 0) return;
    float last_val = x[0] + 1.24f;   // (float)(2*0.12 + 1.0)
    float last_t = 0.0f;
    int ne = 0;
    const float4* x4 = reinterpret_cast<const float4*>(x);
    int t = 0;
    for (int b = 0; b < T / 4; ++b) {
        float4 v = __ldg(&x4[b]);
        float xs[4] = {v.x, v.y, v.z, v.w};
        #pragma unroll
        for (int i = 0; i < 4; ++i) {
            float xt = xs[i];
            if (fabsf(xt - last_val) >= THRESH) {
                g_ev_x[ne]  = xt;
                g_ev_dt[ne] = ((float)t - last_t) / 100.0f;
                g_ev_t[ne]  = t;
                last_val = xt; last_t = (float)t;
                ++ne;
            }
            g_evmap[t] = ne - 1;
            ++t;
        }
    }
    g_ne = ne;
    for (int i = 0; i < 8; ++i) { g_ev_x[ne + i] = 0.f; g_ev_dt[ne + i] = 0.f; }
}

// ---- Pass 2: 8-CTA cluster GRU (R9 champion, event loop unrolled x2 with
//      compile-time phase specialization) ------------------------------------
__global__ void __cluster_dims__(8, 1, 1) __launch_bounds__(NTHREADS, 1)
k_main(const float* __restrict__ w_ih, const float* __restrict__ w_hh,
       const float* __restrict__ b_ih, const float* __restrict__ b_hh)
{
    __shared__ __align__(16) float sh_h[2][H];
    __shared__ __align__(16) float s_red[3][32][12];   // [gate][lane][slot]
    __shared__ __align__(8) unsigned long long s_mbar[2];

    const int tid = threadIdx.x;
    const int w   = tid >> 5;
    const int l   = tid & 31;
    // XOR-swizzled slot: conflict-free STS (R9 win)
    const int slot = w ^ ((l >> 2) & 7);
    const uint32_t rank = my_ctarank();
    const int j = (int)rank * 32 + l;

    // register-resident w_hh rows {j, H+j, 2H+j}, cols [32w, 32w+32)
    unsigned long long wv[3][16];
    #pragma unroll
    for (int g = 0; g < 3; ++g) {
        const ulonglong2* src = reinterpret_cast<const ulonglong2*>(
            w_hh + (size_t)(g * H + j) * H + w * 32);
        #pragma unroll
        for (int i = 0; i < 8; ++i) {
            ulonglong2 q = src[i];
            wv[g][2 * i] = q.x; wv[g][2 * i + 1] = q.y;
        }
    }

    const bool lead = (w == 0);
    float wir0=0,wir1=0,wiz0=0,wiz1=0,win0=0,win1=0,br=0,bz=0,bin=0,bhn=0;
    uint32_t rh[2][8], rb[2][8];
    const uint32_t mb0 = smem_u32(&s_mbar[0]);
    const uint32_t mb1 = smem_u32(&s_mbar[1]);
    if (lead) {
        wir0 = w_ih[(0*H+j)*2+0]; wir1 = w_ih[(0*H+j)*2+1];
        wiz0 = w_ih[(1*H+j)*2+0]; wiz1 = w_ih[(1*H+j)*2+1];
        win0 = w_ih[(2*H+j)*2+0]; win1 = w_ih[(2*H+j)*2+1];
        br  = b_ih[j] + b_hh[j];
        bz  = b_ih[H+j] + b_hh[H+j];
        bin = b_ih[2*H+j];
        bhn = b_hh[2*H+j];
        uint32_t lh0 = smem_u32(&sh_h[0][j]);
        uint32_t lh1 = smem_u32(&sh_h[1][j]);
        #pragma unroll
        for (int i = 0; i < 8; ++i) {
            uint32_t r = (rank + (uint32_t)i) & 7u;   // champion rotation (self first)
            rh[0][i] = mapa_u32(lh0, r); rh[1][i] = mapa_u32(lh1, r);
            rb[0][i] = mapa_u32(mb0, r); rb[1][i] = mapa_u32(mb1, r);
        }
    }

    for (int i = tid; i < 2 * H; i += NTHREADS) ((float*)sh_h)[i] = 0.0f;
    if (tid == 0) {
        MBARRIER_INIT(mb0, 1);
        MBARRIER_INIT(mb1, 1);
        MBARRIER_EXPECT_TX(mb1, 1024);   // step 1
        MBARRIER_EXPECT_TX(mb0, 1024);   // step 2
    }
    __syncthreads();
    CLUSTER_SYNC();

    const int ne = g_ne;
    unsigned par0 = 0, par1 = 0;
    float xc = 0, dc = 0, hprev = 0.0f;
    if (lead) { xc = g_ev_x[0]; dc = g_ev_dt[0]; }

// One event step with compile-time phase P (all phase selects fold away).
#define GRU_STEP(E, P, PARV, MBP)                                                   \
    do {                                                                            \
        const int e = (E);                                                          \
        float xn = 0, dn = 0, air = 0, aiz = 0, ain = 0;                            \
        if (lead) {                                                                 \
            xn = g_ev_x[e + 1]; dn = g_ev_dt[e + 1];                                \
            air = fmaf(wir1, dc, fmaf(wir0, xc, br));                               \
            aiz = fmaf(wiz1, dc, fmaf(wiz0, xc, bz));                               \
            ain = fmaf(win1, dc, fmaf(win0, xc, bin));                              \
        }                                                                           \
        if (e > 0) {                                                                \
            MBARRIER_WAIT((MBP), (PARV));                                           \
            (PARV) ^= 1;                                                            \
            if (tid == 255) MBARRIER_EXPECT_TX((MBP), 1024);   /* rearm e+2 */      \
        }                                                                           \
        const ulonglong2* hb = reinterpret_cast<const ulonglong2*>(&sh_h[P][w * 32]);\
        unsigned long long a0 = 0, a1 = 0, a2 = 0;                                  \
        _Pragma("unroll")                                                           \
        for (int i = 0; i < 8; ++i) {                                               \
            ulonglong2 hv = hb[i];                                                  \
            FMA2(a0, wv[0][2*i], hv.x);  FMA2(a0, wv[0][2*i+1], hv.y);              \
            FMA2(a1, wv[1][2*i], hv.x);  FMA2(a1, wv[1][2*i+1], hv.y);              \
            FMA2(a2, wv[2][2*i], hv.x);  FMA2(a2, wv[2][2*i+1], hv.y);              \
        }                                                                           \
        s_red[0][l][slot] = __uint_as_float((unsigned)a0) + __uint_as_float((unsigned)(a0 >> 32)); \
        s_red[1][l][slot] = __uint_as_float((unsigned)a1) + __uint_as_float((unsigned)(a1 >> 32)); \
        s_red[2][l][slot] = __uint_as_float((unsigned)a2) + __uint_as_float((unsigned)(a2 >> 32)); \
        __syncthreads();                                                            \
        if (lead) {                                                                 \
            float4 r0 = *reinterpret_cast<const float4*>(&s_red[0][l][0]);          \
            float4 r1 = *reinterpret_cast<const float4*>(&s_red[0][l][4]);          \
            float s0 = ((r0.x + r0.y) + (r0.z + r0.w)) + ((r1.x + r1.y) + (r1.z + r1.w)); \
            float tr = tanh_fast(0.5f * (s0 + air));                                \
            float4 n0 = *reinterpret_cast<const float4*>(&s_red[2][l][0]);          \
            float4 n1 = *reinterpret_cast<const float4*>(&s_red[2][l][4]);          \
            float s2 = ((n0.x + n0.y) + (n0.z + n0.w)) + ((n1.x + n1.y) + (n1.z + n1.w)); \
            float hn = s2 + bhn;                                                    \
            float4 z0 = *reinterpret_cast<const float4*>(&s_red[1][l][0]);          \
            float4 z1 = *reinterpret_cast<const float4*>(&s_red[1][l][4]);          \
            float s1 = ((z0.x + z0.y) + (z0.z + z0.w)) + ((z1.x + z1.y) + (z1.z + z1.w)); \
            float rg = fmaf(0.5f, tr, 0.5f);                                        \
            float ng = tanh_fast(fmaf(rg, hn, ain));                                \
            float zg = fmaf(0.5f, tanh_fast(0.5f * (s1 + aiz)), 0.5f);              \
            float hnew = fmaf(zg, hprev - ng, ng);                                  \
            hprev = hnew;                                                           \
            if (e + 1 < ne) {                                                       \
                uint32_t v = __float_as_uint(hnew);                                 \
                _Pragma("unroll")                                                   \
                for (int i = 0; i < 8; ++i)                                         \
                    ST_ASYNC_B32(rh[(P) ^ 1][i], v, rb[(P) ^ 1][i]);                \
            }                                                                       \
            g_hhist[(size_t)e * H + j] = hnew;                                      \
            xc = xn; dc = dn;                                                       \
        }                                                                           \
    } while (0)

    for (int e2 = 0; e2 < ne; e2 += 2) {
        GRU_STEP(e2, 0, par0, mb0);
        if (e2 + 1 < ne) GRU_STEP(e2 + 1, 1, par1, mb1);
    }
#undef GRU_STEP
    CLUSTER_SYNC();
}

// ---- Pass 3a: pred per event (one warp per event) ---------------------------
__global__ void k_pred(const float* __restrict__ w_fc, const float* __restrict__ b_fc) {
    int e = blockIdx.x * 8 + (threadIdx.x >> 5);
    int l = threadIdx.x & 31;
    if (e >= g_ne) return;
    const float4* hr = reinterpret_cast<const float4*>(g_hhist + (size_t)e * H);
    const float4* wf = reinterpret_cast<const float4*>(w_fc);
    float4 h0 = hr[2*l], h1 = hr[2*l+1];
    float4 w0 = __ldg(&wf[2*l]), w1 = __ldg(&wf[2*l+1]);
    float s = h0.x*w0.x + h0.y*w0.y + h0.z*w0.z + h0.w*w0.w
            + h1.x*w1.x + h1.y*w1.y + h1.z*w1.z + h1.w*w1.w;
    #pragma unroll
    for (int o = 16; o > 0; o >>= 1) s += __shfl_xor_sync(0xffffffffu, s, o);
    if (l == 0) g_pred[e] = s + __ldg(b_fc);
}

// ---- Pass 3b: assemble [preds(T) | n_events | idx_padded(T)] ----------------
__global__ void k_out(float* __restrict__ out, int T, int out_size) {
    int t = blockIdx.x * blockDim.x + threadIdx.x;
    if (t >= T) return;
    int ne = g_ne;
    if (t < out_size) {
        int m = g_evmap[t];
        out[t] = (m >= 0) ? g_pred[m] : g_pred[0];
    }
    if (t == 0 && T < out_size) out[T] = (float)ne;
    int k = T + 1 + t;
    if (k < out_size) out[k] = (t < ne) ? (float)g_ev_t[t] : (float)T;
}

extern "C" void kernel_launch(void* const* d_in, const int* in_sizes, int n_in,
                              void* d_out, int out_size) {
    const float* x    = (const float*)d_in[0];
    const float* w_ih = (const float*)d_in[1];
    const float* w_hh = (const float*)d_in[2];
    const float* b_ih = (const float*)d_in[3];
    const float* b_hh = (const float*)d_in[4];
    const float* w_fc = (const float*)d_in[5];
    const float* b_fc = (const float*)d_in[6];
    int T = in_sizes[0];
    if (T > T_MAX) T = T_MAX;
    k_scan<<<1, 32>>>(x, T);
    k_main<<<8, NTHREADS>>>(w_ih, w_hh, b_ih, b_hh);
    k_pred<<<(T + 7) / 8, 256>>>(w_fc, b_fc);
    k_out<<<(T + 255) / 256, 256>>>((float*)d_out, T, out_size);
}